// round 15
// baseline (speedup 1.0000x reference)
#include <cuda_runtime.h>
#include <math_constants.h>

// CropProposals: 3D ROI 2x2x2 adaptive max-pool.
// fm:      (4, 64, 24, 24, 24) f32   -> d_in[0]
// corners: (4, 64, 2, 3)       f32   -> d_in[1]
// out:     (4, 64, 64, 2, 2, 2) f32
//
// 2-D lane mapping: W = z-union width, lane -> (hrel = lane/W, zrel = lane%W);
// one LDG covers R = 32/W h-rows. Per axis both bins have EQUAL length
// m2=(n+1)/2 at lo and lo+n/2 (shared middle slice, max-idempotent). No
// predication: out-of-range lanes clamp onto in-bin duplicate voxels.
// EACH WARP PROCESSES 4 CHANNELS (c0..c0+3) via compile-time immediate
// offsets k*13824 in the LDGs -> 16 independent load streams per step,
// fixed per-warp costs amortized 4x. 2 warps per task split d by parity;
// block = 8 warps = 4 channel-slots x 2 halves sharing one (b,p).
// z-binning via redux.sync on order-preserving keys; halves combined in smem.

#define NEGINF (-CUDART_INF_F)
#define KEY_NEGINF 0x007FFFFFu   // f2key(-inf)
#define CH_STRIDE 13824          // floats per channel volume

__device__ __forceinline__ unsigned f2key(float f) {
    int i = __float_as_int(f);
    return (unsigned)(i ^ ((i >> 31) | 0x80000000));
}
__device__ __forceinline__ float key2f(unsigned u) {
    int i = (int)(u ^ ((~u >> 31) ? 0xFFFFFFFFu : 0x80000000u));
    return __int_as_float(i);
}

__global__ __launch_bounds__(256) void crop_proposals_kernel(
    const float* __restrict__ fm,
    const float* __restrict__ corners,
    float* __restrict__ out)
{
    __shared__ unsigned skey[8][32];      // [warp][ch*8 + slot]

    const int lane  = threadIdx.x & 31;
    const int wid   = threadIdx.x >> 5;   // 0..7
    const int cslot = wid >> 1;           // 0..3 : channel slot (4 ch each)
    const int half  = wid & 1;            // 0/1  : d-parity split

    const int bp = blockIdx.x >> 2;       // b*64 + p
    const int cg = blockIdx.x & 3;        // channel group (16 channels each)
    const int b  = bp >> 6;
    const int c0 = cg * 16 + cslot * 4;   // first of this warp's 4 channels

    // ---- bin computation (matches JAX _pool_masks exactly, fp32) ----
    const float* cor = corners + bp * 6;
    int blo[3], nn[3];
#pragma unroll
    for (int a = 0; a < 3; a++) {
        float ll = __ldg(cor + a)     * 0.25f;
        float ur = __ldg(cor + 3 + a) * 0.25f;
        ll = fminf(fmaxf(ll, 0.0f), 21.0f);
        ur = (ur - ll >= 2.0f) ? ur : (ll + 2.0f);
        ur = fminf(fmaxf(ur, 2.0f), 23.0f);
        int lo = (int)floorf(ll);
        blo[a] = lo;
        nn[a]  = (int)floorf(ur) - lo;   // n in [2, 23]
    }
    // equal-length bins: [lo, lo+m2) and [lo+n/2, lo+n/2+m2), m2 = (n+1)/2
    const int d0   = blo[0], md2 = (nn[0] + 1) >> 1, ddel = (nn[0] >> 1) * 576;
    const int h0   = blo[1], mh2 = (nn[1] + 1) >> 1, hseg = (nn[1] >> 1) * 24;
    const int zlo  = blo[2], mz2 = (nn[2] + 1) >> 1, zhalf = nn[2] >> 1;

    // ---- 2-D lane mapping over (h, z); clamped lanes hit in-bin duplicates ----
    const int W    = nn[2];              // z-union width (2..23)
    const int R    = 32 / W;             // h-rows per load step (1..16)
    const int hrel = lane / W;
    const int zrel = lane - hrel * W;
    const int hcap = mh2 - 1;            // clamp target (inside bin)

    const float* base = fm + ((size_t)(b * 64 + c0)) * CH_STRIDE + (zlo + zrel);

    float acc[4][4];                     // [ch][kx*2+ky]
#pragma unroll
    for (int ch = 0; ch < 4; ch++)
#pragma unroll
        for (int q = 0; q < 4; q++)
            acc[ch][q] = NEGINF;

    // ---- main loop: this warp takes d index i = half, half+2, ... < md2 ----
    for (int i = half; i < md2; i += 2) {
        const float* pA = base + (d0 + i) * 576;   // kx0 stream
        const float* pC = pA + ddel;               // kx1 stream
        for (int idx0 = 0; idx0 < mh2; idx0 += R) {
            const int ro = (h0 + min(idx0 + hrel, hcap)) * 24;
            const float* qA0 = pA + ro;
            const float* qA1 = pA + ro + hseg;
            const float* qC0 = pC + ro;
            const float* qC1 = pC + ro + hseg;
#pragma unroll
            for (int ch = 0; ch < 4; ch++) {      // immediate offsets ch*CH_STRIDE
                acc[ch][0] = fmaxf(acc[ch][0], __ldg(qA0 + ch * CH_STRIDE));
                acc[ch][1] = fmaxf(acc[ch][1], __ldg(qA1 + ch * CH_STRIDE));
                acc[ch][2] = fmaxf(acc[ch][2], __ldg(qC0 + ch * CH_STRIDE));
                acc[ch][3] = fmaxf(acc[ch][3], __ldg(qC1 + ch * CH_STRIDE));
            }
        }
    }

    // ---- per-warp z-bin reductions via redux.sync on monotone keys ----
    unsigned key[4][4];
#pragma unroll
    for (int ch = 0; ch < 4; ch++)
#pragma unroll
        for (int q = 0; q < 4; q++)
            key[ch][q] = f2key(acc[ch][q]);

#pragma unroll
    for (int kz = 0; kz < 2; kz++) {
        const bool inz = (unsigned)(zrel - (kz ? zhalf : 0)) < (unsigned)mz2;
#pragma unroll
        for (int ch = 0; ch < 4; ch++) {
#pragma unroll
            for (int q = 0; q < 4; q++) {     // q = kx*2 + ky
                unsigned mv = __reduce_max_sync(0xFFFFFFFFu,
                                                inz ? key[ch][q] : KEY_NEGINF);
                if (lane == 0)
                    skey[wid][ch * 8 + q * 2 + kz] = mv;
            }
        }
    }
    __syncthreads();

    // ---- combine halves + write: threads 0..127, one output value each ----
    const int tid = threadIdx.x;
    if (tid < 128) {
        const int ocs = tid >> 5;          // channel slot 0..3
        const int ch  = (tid >> 3) & 3;    // channel within slot
        const int k   = tid & 7;           // output slot kx*4+ky*2+kz
        const int s   = ch * 8 + k;
        unsigned v = max(skey[ocs * 2 + 0][s], skey[ocs * 2 + 1][s]);
        const int oc = cg * 16 + ocs * 4 + ch;
        out[(((size_t)bp * 64 + oc) << 3) + k] = key2f(v);
    }
}

extern "C" void kernel_launch(void* const* d_in, const int* in_sizes, int n_in,
                              void* d_out, int out_size)
{
    const float* fm      = (const float*)d_in[0];
    const float* corners = (const float*)d_in[1];
    float* out           = (float*)d_out;

    // 256 (b,p) x 4 channel-groups = 1024 blocks, 8 warps each
    crop_proposals_kernel<<<1024, 256>>>(fm, corners, out);
}